// round 8
// baseline (speedup 1.0000x reference)
#include <cuda_runtime.h>
#include <cuda_bf16.h>
#include <math.h>
#include <stdint.h>

// Problem constants
#define BB 2
#define TT 2048
#define DD 1024
#define HH 16
#define HD 64
#define ROWS (BB*TT)          // 4096

// ---------------- scratch (device globals; no allocations) ----------------
__device__ float g_h   [ROWS * DD];
__device__ float g_qkv [ROWS * 3 * DD];
__device__ float g_att [ROWS * DD];
__device__ float g_x1  [ROWS * DD];
__device__ float g_mid [ROWS * 4 * DD];
// transposed weights
__device__ float g_wqkvT[3 * DD * DD];
__device__ float g_wfcT [DD * DD];
__device__ float g_w1T  [4 * DD * DD];
__device__ float g_w2T  [4 * DD * DD];

// ---------------- helpers -------------------------------------------------
__device__ __forceinline__ uint32_t smem_u32(const void* p) {
    uint32_t a;
    asm("{ .reg .u64 t; cvta.to.shared.u64 t, %1; cvt.u32.u64 %0, t; }"
        : "=r"(a) : "l"(p));
    return a;
}
__device__ __forceinline__ uint32_t f2tf(float f) {
    uint32_t u;
    asm("cvt.rna.tf32.f32 %0, %1;" : "=r"(u) : "f"(f));
    return u;
}
__device__ __forceinline__ void ldsm4(uint32_t& r0, uint32_t& r1,
                                      uint32_t& r2, uint32_t& r3, uint32_t a) {
    asm volatile("ldmatrix.sync.aligned.m8n8.x4.shared.b16 {%0,%1,%2,%3}, [%4];"
                 : "=r"(r0), "=r"(r1), "=r"(r2), "=r"(r3) : "r"(a));
}
__device__ __forceinline__ void mma8(float* c, const uint32_t* a, const uint32_t* b) {
    asm volatile(
        "mma.sync.aligned.m16n8k8.row.col.f32.tf32.tf32.f32 "
        "{%0,%1,%2,%3}, {%4,%5,%6,%7}, {%8,%9}, {%0,%1,%2,%3};"
        : "+f"(c[0]), "+f"(c[1]), "+f"(c[2]), "+f"(c[3])
        : "r"(a[0]), "r"(a[1]), "r"(a[2]), "r"(a[3]), "r"(b[0]), "r"(b[1]));
}
__device__ __forceinline__ void cp16(uint32_t dst, const void* src) {
    asm volatile("cp.async.cg.shared.global [%0], [%1], 16;"
                 :: "r"(dst), "l"(src));
}
__device__ __forceinline__ float gelu_exact(float v) {
    return 0.5f * v * (1.0f + erff(v * 0.70710678118654752f));
}

// ---------------- weight transpose: out[N,K] = in[K,N] --------------------
__global__ void transpose_kernel(const float* __restrict__ in,
                                 float* __restrict__ out, int K, int N) {
    __shared__ float t[32][33];
    int kx = blockIdx.x * 32, ny = blockIdx.y * 32;
    int x = threadIdx.x, y = threadIdx.y;  // 32 x 8
    #pragma unroll
    for (int i = 0; i < 32; i += 8)
        t[y + i][x] = in[(size_t)(kx + y + i) * N + ny + x];
    __syncthreads();
    #pragma unroll
    for (int i = 0; i < 32; i += 8)
        out[(size_t)(ny + y + i) * K + kx + x] = t[x][y + i];
}

// ---------------- LayerNorm ----------------------------------------------
__global__ void ln_kernel(const float* __restrict__ x,
                          const float* __restrict__ g,
                          const float* __restrict__ bvec,
                          float* __restrict__ out) {
    int row = blockIdx.x;
    int t   = threadIdx.x;
    const float4* xr = (const float4*)(x + (size_t)row * DD);
    float4 v = xr[t];
    float s  = v.x + v.y + v.z + v.w;
    float ss = v.x*v.x + v.y*v.y + v.z*v.z + v.w*v.w;
    #pragma unroll
    for (int o = 16; o > 0; o >>= 1) {
        s  += __shfl_xor_sync(0xffffffffu, s,  o);
        ss += __shfl_xor_sync(0xffffffffu, ss, o);
    }
    __shared__ float sh[2][8];
    int w = t >> 5, ln = t & 31;
    if (ln == 0) { sh[0][w] = s; sh[1][w] = ss; }
    __syncthreads();
    s = 0.f; ss = 0.f;
    #pragma unroll
    for (int i = 0; i < 8; i++) { s += sh[0][i]; ss += sh[1][i]; }
    float mu   = s * (1.0f / DD);
    float var  = ss * (1.0f / DD) - mu * mu;
    float rstd = rsqrtf(var + 1e-5f);
    float4 gg = ((const float4*)g)[t];
    float4 bb = ((const float4*)bvec)[t];
    float4 o4;
    o4.x = (v.x - mu) * rstd * gg.x + bb.x;
    o4.y = (v.y - mu) * rstd * gg.y + bb.y;
    o4.z = (v.z - mu) * rstd * gg.z + bb.z;
    o4.w = (v.w - mu) * rstd * gg.w + bb.w;
    ((float4*)(out + (size_t)row * DD))[t] = o4;
}

// ---------------- multistage cp.async tf32 GEMM ---------------------------
// C[M,N] = A[M,K] @ BT[N,K]^T  (+bias / +residual / GELU)
// CTA tile 128x128, BK=32, 3 stages, 512 threads, 16 warps 4(M)x4(N),
// warp tile 32x32 (low regs -> 2 CTAs/SM -> 32 warps resident).
#define GSTG 32768
#define GSMEM (3*GSTG)      // 98304

template <int EPI>
__global__ void __launch_bounds__(512)
gemm_ms(const float* __restrict__ A, const float* __restrict__ BT,
        const float* __restrict__ bias, const float* __restrict__ res,
        float* __restrict__ C, int M, int N, int K) {
    extern __shared__ char smem[];
    const uint32_t sb = smem_u32(smem);
    const int tid  = threadIdx.x;
    const int wid  = tid >> 5;
    const int lane = tid & 31;
    const int m0 = blockIdx.y * 128;
    const int n0 = blockIdx.x * 128;
    const int warp_m = (wid & 3) * 32;
    const int warp_n = (wid >> 2) * 32;

    const int rowA = (lane & 7) + ((lane >> 3) & 1) * 8;
    const int qselA = lane >> 4;
    const int lane7 = lane & 7;
    const int matB  = lane >> 3;

    float acc[2][4][4];
    #pragma unroll
    for (int i = 0; i < 2; i++)
        #pragma unroll
        for (int j = 0; j < 4; j++)
            #pragma unroll
            for (int q = 0; q < 4; q++) acc[i][j][q] = 0.f;

    const int nch = K / 32;

    const float* Abase = A  + (size_t)m0 * K;
    const float* Bbase = BT + (size_t)n0 * K;

    auto load_stage = [&](int stg, int c) {
        const uint32_t ab = sb + stg * GSTG;
        const uint32_t bb = ab + 16384;
        const float* Ap = Abase + (size_t)c * 32;
        const float* Bp = Bbase + (size_t)c * 32;
        #pragma unroll
        for (int i = 0; i < 2; i++) {
            int idx = tid + i * 512;
            int r = idx >> 3, q = idx & 7;
            uint32_t off = (uint32_t)(r * 128 + ((q ^ (r & 7)) * 16));
            cp16(ab + off, Ap + (size_t)r * K + q * 4);
            cp16(bb + off, Bp + (size_t)r * K + q * 4);
        }
    };

    load_stage(0, 0);
    asm volatile("cp.async.commit_group;" ::: "memory");
    if (nch > 1) load_stage(1, 1);
    asm volatile("cp.async.commit_group;" ::: "memory");

    for (int c = 0; c < nch; c++) {
        const int stg = c % 3;
        asm volatile("cp.async.wait_group 1;" ::: "memory");
        __syncthreads();

        if (c + 2 < nch) load_stage((c + 2) % 3, c + 2);
        asm volatile("cp.async.commit_group;" ::: "memory");

        const uint32_t As = sb + stg * GSTG;
        const uint32_t Bs = As + 16384;

        #pragma unroll
        for (int kb = 0; kb < 4; kb++) {
            uint32_t afr[2][4];
            uint32_t bfr[4][2];
            #pragma unroll
            for (int mb = 0; mb < 2; mb++) {
                int row = warp_m + mb * 16 + rowA;
                int quad = (2 * kb + qselA) ^ lane7;
                ldsm4(afr[mb][0], afr[mb][1], afr[mb][2], afr[mb][3],
                      As + (uint32_t)(row * 128 + quad * 16));
            }
            #pragma unroll
            for (int s = 0; s < 2; s++) {
                int nb = 2 * s + (matB >> 1);
                int n = warp_n + nb * 8 + lane7;
                int quad = (2 * kb + (matB & 1)) ^ lane7;
                ldsm4(bfr[2*s][0], bfr[2*s][1], bfr[2*s+1][0], bfr[2*s+1][1],
                      Bs + (uint32_t)(n * 128 + quad * 16));
            }
            #pragma unroll
            for (int mb = 0; mb < 2; mb++)
                #pragma unroll
                for (int nb = 0; nb < 4; nb++)
                    mma8(acc[mb][nb], afr[mb], bfr[nb]);
        }
        __syncthreads();
    }

    // ---- epilogue ----
    const int gr = lane >> 2;
    const int cp = (lane & 3) * 2;
    #pragma unroll
    for (int mb = 0; mb < 2; mb++) {
        #pragma unroll
        for (int nb = 0; nb < 4; nb++) {
            int row0 = m0 + warp_m + mb * 16 + gr;
            int col  = n0 + warp_n + nb * 8 + cp;
            float2 bi = *(const float2*)&bias[col];
            float v0 = acc[mb][nb][0] + bi.x;
            float v1 = acc[mb][nb][1] + bi.y;
            float v2 = acc[mb][nb][2] + bi.x;
            float v3 = acc[mb][nb][3] + bi.y;
            if (EPI == 1) {
                float2 r0 = *(const float2*)&res[(size_t)row0 * N + col];
                float2 r1 = *(const float2*)&res[(size_t)(row0 + 8) * N + col];
                v0 += r0.x; v1 += r0.y; v2 += r1.x; v3 += r1.y;
            }
            if (EPI == 2) {
                v0 = gelu_exact(v0); v1 = gelu_exact(v1);
                v2 = gelu_exact(v2); v3 = gelu_exact(v3);
            }
            *(float2*)&C[(size_t)row0 * N + col]       = make_float2(v0, v1);
            *(float2*)&C[(size_t)(row0 + 8) * N + col] = make_float2(v2, v3);
        }
    }
}

// ---------------- tensor-core flash attention (unchanged) -----------------
#define AQLO 0
#define AQHI 16384
#define AKLO 32768
#define AKHI 49152
#define AVT  65536
#define APS  98304
#define ASMM 163840
#define ASMS 164864
#define ATT_SMEM 165888

__global__ void __launch_bounds__(256)
attn_mma() {
    extern __shared__ char smem[];
    const uint32_t sb = smem_u32(smem);
    float* smf = (float*)smem;

    const int qblk = gridDim.x - 1 - blockIdx.x;
    const int bh = blockIdx.y;
    const int b = bh >> 4, h = bh & 15;
    const int q0 = qblk * 128;

    const float* base = g_qkv + (size_t)b * TT * 3 * DD;
    const float* qb = base + h * HD;
    const float* kb_ = base + DD + h * HD;
    const float* vb = base + 2 * DD + h * HD;

    const int tid = threadIdx.x, wid = tid >> 5, lane = tid & 31;
    const int gr = lane >> 2, qd = lane & 3;
    const int warp_m  = (wid & 3) * 32;
    const int warp_ns = (wid >> 2) * 64;
    const int warp_np = (wid >> 2) * 32;
    const int slot = wid >> 2;

    const int rowA = (lane & 7) + ((lane >> 3) & 1) * 8;
    const int qselA = lane >> 4;
    const int lane7 = lane & 7, matB = lane >> 3;

    #pragma unroll
    for (int i = 0; i < 8; i++) {
        int idx = tid + i * 256;
        int r = idx >> 4, c4 = idx & 15;
        float4 v = *(const float4*)(qb + (size_t)(q0 + r) * 3 * DD + c4 * 4);
        uint32_t off = (c4 < 8 ? AQLO : AQHI) +
                       (uint32_t)(r * 128 + (((c4 & 7) ^ (r & 7)) * 16));
        uint4 u = make_uint4(f2tf(v.x * 0.125f), f2tf(v.y * 0.125f),
                             f2tf(v.z * 0.125f), f2tf(v.w * 0.125f));
        *(uint4*)(smem + off) = u;
    }

    float m_old[4], lsum[4];
    #pragma unroll
    for (int i = 0; i < 4; i++) { m_old[i] = -1e30f; lsum[i] = 0.f; }
    float o[2][4][4];
    #pragma unroll
    for (int mb = 0; mb < 2; mb++)
        #pragma unroll
        for (int nb = 0; nb < 4; nb++)
            #pragma unroll
            for (int q = 0; q < 4; q++) o[mb][nb][q] = 0.f;

    int rloc[4];
    #pragma unroll
    for (int i = 0; i < 4; i++)
        rloc[i] = warp_m + (i >> 1) * 16 + (i & 1) * 8 + gr;

    for (int kt = 0; kt <= qblk; kt++) {
        __syncthreads();

        #pragma unroll
        for (int i = 0; i < 8; i++) {
            int idx = tid + i * 256;
            int r = idx >> 4, c4 = idx & 15;
            float4 v = *(const float4*)(kb_ + (size_t)(kt * 128 + r) * 3 * DD + c4 * 4);
            uint32_t off = (c4 < 8 ? AKLO : AKHI) +
                           (uint32_t)(r * 128 + (((c4 & 7) ^ (r & 7)) * 16));
            *(uint4*)(smem + off) = make_uint4(f2tf(v.x), f2tf(v.y), f2tf(v.z), f2tf(v.w));
        }
        #pragma unroll
        for (int i = 0; i < 2; i++) {
            int lin = tid + i * 256;
            int kq = lin & 31, hq = lin >> 5;
            const float* vp = vb + (size_t)(kt * 128 + kq * 4) * 3 * DD + hq * 4;
            float4 r0 = *(const float4*)(vp);
            float4 r1 = *(const float4*)(vp + 3 * DD);
            float4 r2 = *(const float4*)(vp + 6 * DD);
            float4 r3 = *(const float4*)(vp + 9 * DD);
            float wsx[4] = {r0.x, r1.x, r2.x, r3.x};
            float wsy[4] = {r0.y, r1.y, r2.y, r3.y};
            float wsz[4] = {r0.z, r1.z, r2.z, r3.z};
            float wsw[4] = {r0.w, r1.w, r2.w, r3.w};
            #pragma unroll
            for (int s = 0; s < 4; s++) {
                int t = (s + kq) & 3;
                int hd = hq * 4 + t;
                float* col = (t == 0) ? wsx : (t == 1) ? wsy : (t == 2) ? wsz : wsw;
                uint32_t off = AVT + (kq >> 3) * 8192 +
                               (uint32_t)(hd * 128 + (((kq & 7) ^ (hd & 7)) * 16));
                *(uint4*)(smem + off) =
                    make_uint4(f2tf(col[0]), f2tf(col[1]), f2tf(col[2]), f2tf(col[3]));
            }
        }
        __syncthreads();

        float sacc[2][8][4];
        #pragma unroll
        for (int mb = 0; mb < 2; mb++)
            #pragma unroll
            for (int nb = 0; nb < 8; nb++)
                #pragma unroll
                for (int q = 0; q < 4; q++) sacc[mb][nb][q] = 0.f;

        #pragma unroll
        for (int kb = 0; kb < 8; kb++) {
            const uint32_t Ab = sb + (kb < 4 ? AQLO : AQHI);
            const uint32_t Bb = sb + (kb < 4 ? AKLO : AKHI);
            const int ks = kb & 3;
            uint32_t afr[2][4], bfr[8][2];
            #pragma unroll
            for (int mb = 0; mb < 2; mb++) {
                int row = warp_m + mb * 16 + rowA;
                int quad = (2 * ks + qselA) ^ (rowA & 7);
                ldsm4(afr[mb][0], afr[mb][1], afr[mb][2], afr[mb][3],
                      Ab + (uint32_t)(row * 128 + quad * 16));
            }
            #pragma unroll
            for (int s = 0; s < 4; s++) {
                int nb = 2 * s + (matB >> 1);
                int n = warp_ns + nb * 8 + lane7;
                int quad = (2 * ks + (matB & 1)) ^ lane7;
                ldsm4(bfr[2*s][0], bfr[2*s][1], bfr[2*s+1][0], bfr[2*s+1][1],
                      Bb + (uint32_t)(n * 128 + quad * 16));
            }
            #pragma unroll
            for (int mb = 0; mb < 2; mb++)
                #pragma unroll
                for (int nb = 0; nb < 8; nb++)
                    mma8(sacc[mb][nb], afr[mb], bfr[nb]);
        }

        if (kt == qblk) {
            #pragma unroll
            for (int mb = 0; mb < 2; mb++)
                #pragma unroll
                for (int half = 0; half < 2; half++) {
                    int rowg = q0 + rloc[mb * 2 + half];
                    #pragma unroll
                    for (int nb = 0; nb < 8; nb++)
                        #pragma unroll
                        for (int j = 0; j < 2; j++) {
                            int col = kt * 128 + warp_ns + nb * 8 + 2 * qd + j;
                            if (col > rowg) sacc[mb][nb][half * 2 + j] = -1e30f;
                        }
                }
        }

        float mt[4];
        #pragma unroll
        for (int i = 0; i < 4; i++) {
            int mb = i >> 1, half = i & 1;
            float v = -1e30f;
            #pragma unroll
            for (int nb = 0; nb < 8; nb++) {
                v = fmaxf(v, sacc[mb][nb][half * 2 + 0]);
                v = fmaxf(v, sacc[mb][nb][half * 2 + 1]);
            }
            v = fmaxf(v, __shfl_xor_sync(0xffffffffu, v, 1));
            v = fmaxf(v, __shfl_xor_sync(0xffffffffu, v, 2));
            mt[i] = v;
        }
        if (qd == 0) {
            #pragma unroll
            for (int i = 0; i < 4; i++)
                smf[(ASMM >> 2) + slot * 128 + rloc[i]] = mt[i];
        }
        __syncthreads();

        float mnew[4], sc[4];
        #pragma unroll
        for (int i = 0; i < 4; i++) {
            float mfull = fmaxf(smf[(ASMM >> 2) + rloc[i]],
                                smf[(ASMM >> 2) + 128 + rloc[i]]);
            mnew[i] = fmaxf(m_old[i], mfull);
            sc[i] = __expf(m_old[i] - mnew[i]);
            m_old[i] = mnew[i];
        }

        float ts[4] = {0.f, 0.f, 0.f, 0.f};
        #pragma unroll
        for (int mb = 0; mb < 2; mb++)
            #pragma unroll
            for (int half = 0; half < 2; half++) {
                int i = mb * 2 + half;
                #pragma unroll
                for (int nb = 0; nb < 8; nb++) {
                    float p0 = __expf(sacc[mb][nb][half * 2 + 0] - mnew[i]);
                    float p1 = __expf(sacc[mb][nb][half * 2 + 1] - mnew[i]);
                    sacc[mb][nb][half * 2 + 0] = p0;
                    sacc[mb][nb][half * 2 + 1] = p1;
                    ts[i] += p0 + p1;
                }
            }
        #pragma unroll
        for (int i = 0; i < 4; i++) {
            ts[i] += __shfl_xor_sync(0xffffffffu, ts[i], 1);
            ts[i] += __shfl_xor_sync(0xffffffffu, ts[i], 2);
        }
        if (qd == 0) {
            #pragma unroll
            for (int i = 0; i < 4; i++)
                smf[(ASMS >> 2) + slot * 128 + rloc[i]] = ts[i];
        }
        #pragma unroll
        for (int mb = 0; mb < 2; mb++)
            #pragma unroll
            for (int nb = 0; nb < 4; nb++) {
                o[mb][nb][0] *= sc[mb * 2 + 0];
                o[mb][nb][1] *= sc[mb * 2 + 0];
                o[mb][nb][2] *= sc[mb * 2 + 1];
                o[mb][nb][3] *= sc[mb * 2 + 1];
            }
        #pragma unroll
        for (int i = 0; i < 4; i++) lsum[i] *= sc[i];
        __syncthreads();
        #pragma unroll
        for (int i = 0; i < 4; i++)
            lsum[i] += smf[(ASMS >> 2) + rloc[i]] + smf[(ASMS >> 2) + 128 + rloc[i]];

        #pragma unroll
        for (int mb = 0; mb < 2; mb++)
            #pragma unroll
            for (int half = 0; half < 2; half++) {
                int row = rloc[mb * 2 + half];
                #pragma unroll
                for (int nb = 0; nb < 8; nb++) {
                    int col0 = warp_ns + nb * 8 + 2 * qd;
                    int cbuf = col0 >> 5, c5 = col0 & 31;
                    uint32_t addr = APS + cbuf * 16384 +
                        (uint32_t)(row * 128 + (((c5 >> 2) ^ (row & 7)) * 16) + (c5 & 3) * 4);
                    uint2 u = make_uint2(f2tf(sacc[mb][nb][half * 2 + 0]),
                                         f2tf(sacc[mb][nb][half * 2 + 1]));
                    *(uint2*)(smem + addr) = u;
                }
            }
        __syncthreads();

        #pragma unroll
        for (int ksx = 0; ksx < 16; ksx++) {
            const uint32_t Pb = sb + APS + (ksx >> 2) * 16384;
            const uint32_t Vb = sb + AVT + (ksx >> 2) * 8192;
            const int kk = ksx & 3;
            uint32_t afr[2][4], bfr[4][2];
            #pragma unroll
            for (int mb = 0; mb < 2; mb++) {
                int row = warp_m + mb * 16 + rowA;
                int quad = (2 * kk + qselA) ^ (rowA & 7);
                ldsm4(afr[mb][0], afr[mb][1], afr[mb][2], afr[mb][3],
                      Pb + (uint32_t)(row * 128 + quad * 16));
            }
            #pragma unroll
            for (int s = 0; s < 2; s++) {
                int nb = 2 * s + (matB >> 1);
                int n = warp_np + nb * 8 + lane7;
                int quad = (2 * kk + (matB & 1)) ^ lane7;
                ldsm4(bfr[2*s][0], bfr[2*s][1], bfr[2*s+1][0], bfr[2*s+1][1],
                      Vb + (uint32_t)(n * 128 + quad * 16));
            }
            #pragma unroll
            for (int mb = 0; mb < 2; mb++)
                #pragma unroll
                for (int nb = 0; nb < 4; nb++)
                    mma8(o[mb][nb], afr[mb], bfr[nb]);
        }
    }

    float inv[4];
    #pragma unroll
    for (int i = 0; i < 4; i++) inv[i] = 1.0f / lsum[i];
    #pragma unroll
    for (int mb = 0; mb < 2; mb++)
        #pragma unroll
        for (int half = 0; half < 2; half++) {
            int i = mb * 2 + half;
            int row = q0 + rloc[i];
            #pragma unroll
            for (int nb = 0; nb < 4; nb++) {
                int col = warp_np + nb * 8 + 2 * qd;
                float2 w = make_float2(o[mb][nb][half * 2 + 0] * inv[i],
                                       o[mb][nb][half * 2 + 1] * inv[i]);
                *(float2*)&g_att[((size_t)b * TT + row) * DD + h * HD + col] = w;
            }
        }
}

// ---------------- launch -------------------------------------------------
extern "C" void kernel_launch(void* const* d_in, const int* in_sizes, int n_in,
                              void* d_out, int out_size) {
    const float* x     = (const float*)d_in[0];
    const float* w_qkv = (const float*)d_in[1];
    const float* b_qkv = (const float*)d_in[2];
    const float* w_fc  = (const float*)d_in[3];
    const float* b_fc  = (const float*)d_in[4];
    const float* ln1_g = (const float*)d_in[5];
    const float* ln1_b = (const float*)d_in[6];
    const float* ln2_g = (const float*)d_in[7];
    const float* ln2_b = (const float*)d_in[8];
    const float* w1    = (const float*)d_in[9];
    const float* b1    = (const float*)d_in[10];
    const float* w2    = (const float*)d_in[11];
    const float* b2    = (const float*)d_in[12];
    float* out = (float*)d_out;

    float *p_h, *p_qkv, *p_att, *p_x1, *p_mid;
    float *p_wqkvT, *p_wfcT, *p_w1T, *p_w2T;
    cudaGetSymbolAddress((void**)&p_h,    g_h);
    cudaGetSymbolAddress((void**)&p_qkv,  g_qkv);
    cudaGetSymbolAddress((void**)&p_att,  g_att);
    cudaGetSymbolAddress((void**)&p_x1,   g_x1);
    cudaGetSymbolAddress((void**)&p_mid,  g_mid);
    cudaGetSymbolAddress((void**)&p_wqkvT, g_wqkvT);
    cudaGetSymbolAddress((void**)&p_wfcT,  g_wfcT);
    cudaGetSymbolAddress((void**)&p_w1T,   g_w1T);
    cudaGetSymbolAddress((void**)&p_w2T,   g_w2T);

    cudaFuncSetAttribute(gemm_ms<0>, cudaFuncAttributeMaxDynamicSharedMemorySize, GSMEM);
    cudaFuncSetAttribute(gemm_ms<1>, cudaFuncAttributeMaxDynamicSharedMemorySize, GSMEM);
    cudaFuncSetAttribute(gemm_ms<2>, cudaFuncAttributeMaxDynamicSharedMemorySize, GSMEM);
    cudaFuncSetAttribute(attn_mma,   cudaFuncAttributeMaxDynamicSharedMemorySize, ATT_SMEM);

    dim3 tb(32, 8);
    // 0) transpose weights
    transpose_kernel<<<dim3(DD/32, 3*DD/32), tb>>>(w_qkv, p_wqkvT, DD, 3*DD);
    transpose_kernel<<<dim3(DD/32, DD/32),   tb>>>(w_fc,  p_wfcT,  DD, DD);
    transpose_kernel<<<dim3(DD/32, 4*DD/32), tb>>>(w1,    p_w1T,   DD, 4*DD);
    transpose_kernel<<<dim3(4*DD/32, DD/32), tb>>>(w2,    p_w2T,   4*DD, DD);

    // 1) h = LN1(x)
    ln_kernel<<<ROWS, 256>>>(x, ln1_g, ln1_b, p_h);

    // 2) qkv = h @ w_qkv + b_qkv              [4096 x 3072]
    gemm_ms<0><<<dim3(3*DD/128, ROWS/128), 512, GSMEM>>>(
        p_h, p_wqkvT, b_qkv, nullptr, p_qkv, ROWS, 3*DD, DD);

    // 3) causal attention -> g_att            [4096 x 1024]
    attn_mma<<<dim3(TT/128, BB*HH), 256, ATT_SMEM>>>();

    // 4) x1 = x + att @ w_fc + b_fc           [4096 x 1024]
    gemm_ms<1><<<dim3(DD/128, ROWS/128), 512, GSMEM>>>(
        p_att, p_wfcT, b_fc, x, p_x1, ROWS, DD, DD);

    // 5) h = LN2(x1)
    ln_kernel<<<ROWS, 256>>>(p_x1, ln2_g, ln2_b, p_h);

    // 6) mid = gelu(h @ w1 + b1)              [4096 x 4096]
    gemm_ms<2><<<dim3(4*DD/128, ROWS/128), 512, GSMEM>>>(
        p_h, p_w1T, b1, nullptr, p_mid, ROWS, 4*DD, DD);

    // 7) out = x1 + mid @ w2 + b2             [4096 x 1024]
    gemm_ms<1><<<dim3(DD/128, ROWS/128), 512, GSMEM>>>(
        p_mid, p_w2T, b2, p_x1, out, ROWS, DD, 4*DD);
}

// round 14
// speedup vs baseline: 1.5700x; 1.5700x over previous
#include <cuda_runtime.h>
#include <cuda_bf16.h>
#include <cuda_fp16.h>
#include <math.h>
#include <stdint.h>

// Problem constants
#define BB 2
#define TT 2048
#define DD 1024
#define HH 16
#define HD 64
#define ROWS (BB*TT)          // 4096

// ---------------- scratch (device globals; no allocations) ----------------
__device__ __half g_hh  [ROWS * DD];        // LN outputs (half)
__device__ float  g_qkv [ROWS * 3 * DD];    // QKV (fp32, attention reads)
__device__ __half g_atth[ROWS * DD];        // attention out (half)
__device__ float  g_x1  [ROWS * DD];        // residual stream (fp32)
__device__ __half g_midh[ROWS * 4 * DD];    // MLP hidden (half)
// transposed weights (half)
__device__ __half g_wqkvT[3 * DD * DD];
__device__ __half g_wfcT [DD * DD];
__device__ __half g_w1T  [4 * DD * DD];
__device__ __half g_w2T  [4 * DD * DD];

// ---------------- helpers -------------------------------------------------
__device__ __forceinline__ uint32_t smem_u32(const void* p) {
    uint32_t a;
    asm("{ .reg .u64 t; cvta.to.shared.u64 t, %1; cvt.u32.u64 %0, t; }"
        : "=r"(a) : "l"(p));
    return a;
}
__device__ __forceinline__ uint32_t f2tf(float f) {
    uint32_t u;
    asm("cvt.rna.tf32.f32 %0, %1;" : "=r"(u) : "f"(f));
    return u;
}
__device__ __forceinline__ void ldsm4(uint32_t& r0, uint32_t& r1,
                                      uint32_t& r2, uint32_t& r3, uint32_t a) {
    asm volatile("ldmatrix.sync.aligned.m8n8.x4.shared.b16 {%0,%1,%2,%3}, [%4];"
                 : "=r"(r0), "=r"(r1), "=r"(r2), "=r"(r3) : "r"(a));
}
// tf32 k8 mma (attention)
__device__ __forceinline__ void mma8(float* c, const uint32_t* a, const uint32_t* b) {
    asm volatile(
        "mma.sync.aligned.m16n8k8.row.col.f32.tf32.tf32.f32 "
        "{%0,%1,%2,%3}, {%4,%5,%6,%7}, {%8,%9}, {%0,%1,%2,%3};"
        : "+f"(c[0]), "+f"(c[1]), "+f"(c[2]), "+f"(c[3])
        : "r"(a[0]), "r"(a[1]), "r"(a[2]), "r"(a[3]), "r"(b[0]), "r"(b[1]));
}
// f16 k16 mma (GEMMs)
__device__ __forceinline__ void mma16(float* c, const uint32_t* a, const uint32_t* b) {
    asm volatile(
        "mma.sync.aligned.m16n8k16.row.col.f32.f16.f16.f32 "
        "{%0,%1,%2,%3}, {%4,%5,%6,%7}, {%8,%9}, {%0,%1,%2,%3};"
        : "+f"(c[0]), "+f"(c[1]), "+f"(c[2]), "+f"(c[3])
        : "r"(a[0]), "r"(a[1]), "r"(a[2]), "r"(a[3]), "r"(b[0]), "r"(b[1]));
}
__device__ __forceinline__ void cp16(uint32_t dst, const void* src) {
    asm volatile("cp.async.cg.shared.global [%0], [%1], 16;"
                 :: "r"(dst), "l"(src));
}
__device__ __forceinline__ float gelu_exact(float v) {
    return 0.5f * v * (1.0f + erff(v * 0.70710678118654752f));
}

// ---------------- weight transpose: out[N,K] = half(in[K,N]) --------------
__global__ void transpose_kernel(const float* __restrict__ in,
                                 __half* __restrict__ out, int K, int N) {
    __shared__ float t[32][33];
    int kx = blockIdx.x * 32, ny = blockIdx.y * 32;
    int x = threadIdx.x, y = threadIdx.y;  // 32 x 8
    #pragma unroll
    for (int i = 0; i < 32; i += 8)
        t[y + i][x] = in[(size_t)(kx + y + i) * N + ny + x];
    __syncthreads();
    #pragma unroll
    for (int i = 0; i < 32; i += 8)
        out[(size_t)(ny + y + i) * K + kx + x] = __float2half(t[x][y + i]);
}

// ---------------- LayerNorm (half output) ---------------------------------
__global__ void ln_kernel(const float* __restrict__ x,
                          const float* __restrict__ g,
                          const float* __restrict__ bvec,
                          __half* __restrict__ out) {
    int row = blockIdx.x;
    int t   = threadIdx.x;
    const float4* xr = (const float4*)(x + (size_t)row * DD);
    float4 v = xr[t];
    float s  = v.x + v.y + v.z + v.w;
    float ss = v.x*v.x + v.y*v.y + v.z*v.z + v.w*v.w;
    #pragma unroll
    for (int o = 16; o > 0; o >>= 1) {
        s  += __shfl_xor_sync(0xffffffffu, s,  o);
        ss += __shfl_xor_sync(0xffffffffu, ss, o);
    }
    __shared__ float sh[2][8];
    int w = t >> 5, ln = t & 31;
    if (ln == 0) { sh[0][w] = s; sh[1][w] = ss; }
    __syncthreads();
    s = 0.f; ss = 0.f;
    #pragma unroll
    for (int i = 0; i < 8; i++) { s += sh[0][i]; ss += sh[1][i]; }
    float mu   = s * (1.0f / DD);
    float var  = ss * (1.0f / DD) - mu * mu;
    float rstd = rsqrtf(var + 1e-5f);
    float4 gg = ((const float4*)g)[t];
    float4 bb = ((const float4*)bvec)[t];
    float4 o4;
    o4.x = (v.x - mu) * rstd * gg.x + bb.x;
    o4.y = (v.y - mu) * rstd * gg.y + bb.y;
    o4.z = (v.z - mu) * rstd * gg.z + bb.z;
    o4.w = (v.w - mu) * rstd * gg.w + bb.w;
    __half2 ha = __floats2half2_rn(o4.x, o4.y);
    __half2 hb = __floats2half2_rn(o4.z, o4.w);
    uint2 u = make_uint2(*(uint32_t*)&ha, *(uint32_t*)&hb);
    ((uint2*)(out + (size_t)row * DD))[t] = u;
}

// ---------------- multistage cp.async fp16 GEMM ---------------------------
// C[M,N] = A[M,K] @ BT[N,K]^T, fp16 inputs, fp32 accum.
// CTA tile 128x128, BK=64, 3 stages, 256 threads, warp grid 2(M)x4(N),
// warp tile 64x32. Rows: 64 halves = 128B, quad^(row&7) swizzle.
// All pointer args are always valid (no nullptr at call sites); unused
// ones (per EPI) are never dereferenced.
#define GSTG 32768          // 16KB A + 16KB B
#define GSMEM (3*GSTG)      // 98304

// EPI: 0 = +bias -> fp32 C ; 1 = +bias+residual -> fp32 C ;
// 2 = gelu(+bias) -> half Ch only
template <int EPI>
__global__ void __launch_bounds__(256)
gemm_h(const __half* __restrict__ A, const __half* __restrict__ BT,
       const float* __restrict__ bias, const float* __restrict__ res,
       float* __restrict__ C, __half* __restrict__ Ch, int M, int N, int K) {
    extern __shared__ char smem[];
    const uint32_t sb = smem_u32(smem);
    const int tid  = threadIdx.x;
    const int wid  = tid >> 5;
    const int lane = tid & 31;
    const int m0 = blockIdx.y * 128;
    const int n0 = blockIdx.x * 128;
    const int warp_m = (wid & 1) * 64;
    const int warp_n = (wid >> 1) * 32;

    const int rowA = (lane & 7) + ((lane >> 3) & 1) * 8;   // a-frag row
    const int qselA = lane >> 4;                           // a-frag k-half
    const int nB = (lane & 7) + (lane >> 4) * 8;           // b-frag n row
    const int qselB = (lane >> 3) & 1;                     // b-frag k-half

    float acc[4][4][4];
    #pragma unroll
    for (int i = 0; i < 4; i++)
        #pragma unroll
        for (int j = 0; j < 4; j++)
            #pragma unroll
            for (int q = 0; q < 4; q++) acc[i][j][q] = 0.f;

    const int nch = K / 64;

    const __half* Abase = A  + (size_t)m0 * K;
    const __half* Bbase = BT + (size_t)n0 * K;

    auto load_stage = [&](int stg, int c) {
        const uint32_t ab = sb + stg * GSTG;
        const uint32_t bb = ab + 16384;
        const __half* Ap = Abase + (size_t)c * 64;
        const __half* Bp = Bbase + (size_t)c * 64;
        #pragma unroll
        for (int i = 0; i < 4; i++) {
            int idx = tid + i * 256;
            int r = idx >> 3, q = idx & 7;
            uint32_t off = (uint32_t)(r * 128 + ((q ^ (r & 7)) * 16));
            cp16(ab + off, Ap + (size_t)r * K + q * 8);
            cp16(bb + off, Bp + (size_t)r * K + q * 8);
        }
    };

    load_stage(0, 0);
    asm volatile("cp.async.commit_group;" ::: "memory");
    if (nch > 1) load_stage(1, 1);
    asm volatile("cp.async.commit_group;" ::: "memory");

    for (int c = 0; c < nch; c++) {
        const int stg = c % 3;
        asm volatile("cp.async.wait_group 1;" ::: "memory");
        __syncthreads();

        if (c + 2 < nch) load_stage((c + 2) % 3, c + 2);
        asm volatile("cp.async.commit_group;" ::: "memory");

        const uint32_t As = sb + stg * GSTG;
        const uint32_t Bs = As + 16384;

        #pragma unroll
        for (int ks = 0; ks < 4; ks++) {    // 4 x k16 = BK 64
            uint32_t afr[4][4];
            uint32_t bfr[4][2];
            #pragma unroll
            for (int mb = 0; mb < 4; mb++) {
                int row = warp_m + mb * 16 + rowA;
                int quad = (2 * ks + qselA) ^ (row & 7);
                ldsm4(afr[mb][0], afr[mb][1], afr[mb][2], afr[mb][3],
                      As + (uint32_t)(row * 128 + quad * 16));
            }
            #pragma unroll
            for (int pair = 0; pair < 2; pair++) {
                int n = warp_n + pair * 16 + nB;
                int quad = (2 * ks + qselB) ^ (n & 7);
                ldsm4(bfr[2*pair][0], bfr[2*pair][1],
                      bfr[2*pair+1][0], bfr[2*pair+1][1],
                      Bs + (uint32_t)(n * 128 + quad * 16));
            }
            #pragma unroll
            for (int mb = 0; mb < 4; mb++)
                #pragma unroll
                for (int nb = 0; nb < 4; nb++)
                    mma16(acc[mb][nb], afr[mb], bfr[nb]);
        }
        __syncthreads();
    }

    // ---- epilogue ----
    const int gr = lane >> 2;
    const int cp = (lane & 3) * 2;
    #pragma unroll
    for (int mb = 0; mb < 4; mb++) {
        #pragma unroll
        for (int nb = 0; nb < 4; nb++) {
            int row0 = m0 + warp_m + mb * 16 + gr;
            int col  = n0 + warp_n + nb * 8 + cp;
            float2 bi = *(const float2*)&bias[col];
            float v0 = acc[mb][nb][0] + bi.x;
            float v1 = acc[mb][nb][1] + bi.y;
            float v2 = acc[mb][nb][2] + bi.x;
            float v3 = acc[mb][nb][3] + bi.y;
            if (EPI == 1) {
                float2 r0 = *(const float2*)&res[(size_t)row0 * N + col];
                float2 r1 = *(const float2*)&res[(size_t)(row0 + 8) * N + col];
                v0 += r0.x; v1 += r0.y; v2 += r1.x; v3 += r1.y;
            }
            if (EPI == 2) {
                v0 = gelu_exact(v0); v1 = gelu_exact(v1);
                v2 = gelu_exact(v2); v3 = gelu_exact(v3);
                *(__half2*)&Ch[(size_t)row0 * N + col]       = __floats2half2_rn(v0, v1);
                *(__half2*)&Ch[(size_t)(row0 + 8) * N + col] = __floats2half2_rn(v2, v3);
            } else {
                *(float2*)&C[(size_t)row0 * N + col]       = make_float2(v0, v1);
                *(float2*)&C[(size_t)(row0 + 8) * N + col] = make_float2(v2, v3);
            }
        }
    }
}

// ---------------- tensor-core flash attention (tf32; half output) ---------
#define AQLO 0
#define AQHI 16384
#define AKLO 32768
#define AKHI 49152
#define AVT  65536
#define APS  98304
#define ASMM 163840
#define ASMS 164864
#define ATT_SMEM 165888

__global__ void __launch_bounds__(256)
attn_mma() {
    extern __shared__ char smem[];
    const uint32_t sb = smem_u32(smem);
    float* smf = (float*)smem;

    const int qblk = gridDim.x - 1 - blockIdx.x;
    const int bh = blockIdx.y;
    const int b = bh >> 4, h = bh & 15;
    const int q0 = qblk * 128;

    const float* base = g_qkv + (size_t)b * TT * 3 * DD;
    const float* qb = base + h * HD;
    const float* kb_ = base + DD + h * HD;
    const float* vb = base + 2 * DD + h * HD;

    const int tid = threadIdx.x, wid = tid >> 5, lane = tid & 31;
    const int gr = lane >> 2, qd = lane & 3;
    const int warp_m  = (wid & 3) * 32;
    const int warp_ns = (wid >> 2) * 64;
    const int warp_np = (wid >> 2) * 32;
    const int slot = wid >> 2;

    const int rowA = (lane & 7) + ((lane >> 3) & 1) * 8;
    const int qselA = lane >> 4;
    const int lane7 = lane & 7, matB = lane >> 3;

    #pragma unroll
    for (int i = 0; i < 8; i++) {
        int idx = tid + i * 256;
        int r = idx >> 4, c4 = idx & 15;
        float4 v = *(const float4*)(qb + (size_t)(q0 + r) * 3 * DD + c4 * 4);
        uint32_t off = (c4 < 8 ? AQLO : AQHI) +
                       (uint32_t)(r * 128 + (((c4 & 7) ^ (r & 7)) * 16));
        uint4 u = make_uint4(f2tf(v.x * 0.125f), f2tf(v.y * 0.125f),
                             f2tf(v.z * 0.125f), f2tf(v.w * 0.125f));
        *(uint4*)(smem + off) = u;
    }

    float m_old[4], lsum[4];
    #pragma unroll
    for (int i = 0; i < 4; i++) { m_old[i] = -1e30f; lsum[i] = 0.f; }
    float o[2][4][4];
    #pragma unroll
    for (int mb = 0; mb < 2; mb++)
        #pragma unroll
        for (int nb = 0; nb < 4; nb++)
            #pragma unroll
            for (int q = 0; q < 4; q++) o[mb][nb][q] = 0.f;

    int rloc[4];
    #pragma unroll
    for (int i = 0; i < 4; i++)
        rloc[i] = warp_m + (i >> 1) * 16 + (i & 1) * 8 + gr;

    for (int kt = 0; kt <= qblk; kt++) {
        __syncthreads();

        #pragma unroll
        for (int i = 0; i < 8; i++) {
            int idx = tid + i * 256;
            int r = idx >> 4, c4 = idx & 15;
            float4 v = *(const float4*)(kb_ + (size_t)(kt * 128 + r) * 3 * DD + c4 * 4);
            uint32_t off = (c4 < 8 ? AKLO : AKHI) +
                           (uint32_t)(r * 128 + (((c4 & 7) ^ (r & 7)) * 16));
            *(uint4*)(smem + off) = make_uint4(f2tf(v.x), f2tf(v.y), f2tf(v.z), f2tf(v.w));
        }
        #pragma unroll
        for (int i = 0; i < 2; i++) {
            int lin = tid + i * 256;
            int kq = lin & 31, hq = lin >> 5;
            const float* vp = vb + (size_t)(kt * 128 + kq * 4) * 3 * DD + hq * 4;
            float4 r0 = *(const float4*)(vp);
            float4 r1 = *(const float4*)(vp + 3 * DD);
            float4 r2 = *(const float4*)(vp + 6 * DD);
            float4 r3 = *(const float4*)(vp + 9 * DD);
            float wsx[4] = {r0.x, r1.x, r2.x, r3.x};
            float wsy[4] = {r0.y, r1.y, r2.y, r3.y};
            float wsz[4] = {r0.z, r1.z, r2.z, r3.z};
            float wsw[4] = {r0.w, r1.w, r2.w, r3.w};
            #pragma unroll
            for (int s = 0; s < 4; s++) {
                int t = (s + kq) & 3;
                int hd = hq * 4 + t;
                float* col = (t == 0) ? wsx : (t == 1) ? wsy : (t == 2) ? wsz : wsw;
                uint32_t off = AVT + (kq >> 3) * 8192 +
                               (uint32_t)(hd * 128 + (((kq & 7) ^ (hd & 7)) * 16));
                *(uint4*)(smem + off) =
                    make_uint4(f2tf(col[0]), f2tf(col[1]), f2tf(col[2]), f2tf(col[3]));
            }
        }
        __syncthreads();

        float sacc[2][8][4];
        #pragma unroll
        for (int mb = 0; mb < 2; mb++)
            #pragma unroll
            for (int nb = 0; nb < 8; nb++)
                #pragma unroll
                for (int q = 0; q < 4; q++) sacc[mb][nb][q] = 0.f;

        #pragma unroll
        for (int kb = 0; kb < 8; kb++) {
            const uint32_t Ab = sb + (kb < 4 ? AQLO : AQHI);
            const uint32_t Bb = sb + (kb < 4 ? AKLO : AKHI);
            const int ks = kb & 3;
            uint32_t afr[2][4], bfr[8][2];
            #pragma unroll
            for (int mb = 0; mb < 2; mb++) {
                int row = warp_m + mb * 16 + rowA;
                int quad = (2 * ks + qselA) ^ (rowA & 7);
                ldsm4(afr[mb][0], afr[mb][1], afr[mb][2], afr[mb][3],
                      Ab + (uint32_t)(row * 128 + quad * 16));
            }
            #pragma unroll
            for (int s = 0; s < 4; s++) {
                int nb = 2 * s + (matB >> 1);
                int n = warp_ns + nb * 8 + lane7;
                int quad = (2 * ks + (matB & 1)) ^ lane7;
                ldsm4(bfr[2*s][0], bfr[2*s][1], bfr[2*s+1][0], bfr[2*s+1][1],
                      Bb + (uint32_t)(n * 128 + quad * 16));
            }
            #pragma unroll
            for (int mb = 0; mb < 2; mb++)
                #pragma unroll
                for (int nb = 0; nb < 8; nb++)
                    mma8(sacc[mb][nb], afr[mb], bfr[nb]);
        }

        if (kt == qblk) {
            #pragma unroll
            for (int mb = 0; mb < 2; mb++)
                #pragma unroll
                for (int half = 0; half < 2; half++) {
                    int rowg = q0 + rloc[mb * 2 + half];
                    #pragma unroll
                    for (int nb = 0; nb < 8; nb++)
                        #pragma unroll
                        for (int j = 0; j < 2; j++) {
                            int col = kt * 128 + warp_ns + nb * 8 + 2 * qd + j;
                            if (col > rowg) sacc[mb][nb][half * 2 + j] = -1e30f;
                        }
                }
        }

        float mt[4];
        #pragma unroll
        for (int i = 0; i < 4; i++) {
            int mb = i >> 1, half = i & 1;
            float v = -1e30f;
            #pragma unroll
            for (int nb = 0; nb < 8; nb++) {
                v = fmaxf(v, sacc[mb][nb][half * 2 + 0]);
                v = fmaxf(v, sacc[mb][nb][half * 2 + 1]);
            }
            v = fmaxf(v, __shfl_xor_sync(0xffffffffu, v, 1));
            v = fmaxf(v, __shfl_xor_sync(0xffffffffu, v, 2));
            mt[i] = v;
        }
        if (qd == 0) {
            #pragma unroll
            for (int i = 0; i < 4; i++)
                smf[(ASMM >> 2) + slot * 128 + rloc[i]] = mt[i];
        }
        __syncthreads();

        float mnew[4], sc[4];
        #pragma unroll
        for (int i = 0; i < 4; i++) {
            float mfull = fmaxf(smf[(ASMM >> 2) + rloc[i]],
                                smf[(ASMM >> 2) + 128 + rloc[i]]);
            mnew[i] = fmaxf(m_old[i], mfull);
            sc[i] = __expf(m_old[i] - mnew[i]);
            m_old[i] = mnew[i];
        }

        float ts[4] = {0.f, 0.f, 0.f, 0.f};
        #pragma unroll
        for (int mb = 0; mb < 2; mb++)
            #pragma unroll
            for (int half = 0; half < 2; half++) {
                int i = mb * 2 + half;
                #pragma unroll
                for (int nb = 0; nb < 8; nb++) {
                    float p0 = __expf(sacc[mb][nb][half * 2 + 0] - mnew[i]);
                    float p1 = __expf(sacc[mb][nb][half * 2 + 1] - mnew[i]);
                    sacc[mb][nb][half * 2 + 0] = p0;
                    sacc[mb][nb][half * 2 + 1] = p1;
                    ts[i] += p0 + p1;
                }
            }
        #pragma unroll
        for (int i = 0; i < 4; i++) {
            ts[i] += __shfl_xor_sync(0xffffffffu, ts[i], 1);
            ts[i] += __shfl_xor_sync(0xffffffffu, ts[i], 2);
        }
        if (qd == 0) {
            #pragma unroll
            for (int i = 0; i < 4; i++)
                smf[(ASMS >> 2) + slot * 128 + rloc[i]] = ts[i];
        }
        #pragma unroll
        for (int mb = 0; mb < 2; mb++)
            #pragma unroll
            for (int nb = 0; nb < 4; nb++) {
                o[mb][nb][0] *= sc[mb * 2 + 0];
                o[mb][nb][1] *= sc[mb * 2 + 0];
                o[mb][nb][2] *= sc[mb * 2 + 1];
                o[mb][nb][3] *= sc[mb * 2 + 1];
            }
        #pragma unroll
        for (int i = 0; i < 4; i++) lsum[i] *= sc[i];
        __syncthreads();
        #pragma unroll
        for (int i = 0; i < 4; i++)
            lsum[i] += smf[(ASMS >> 2) + rloc[i]] + smf[(ASMS >> 2) + 128 + rloc[i]];

        #pragma unroll
        for (int mb = 0; mb < 2; mb++)
            #pragma unroll
            for (int half = 0; half < 2; half++) {
                int row = rloc[mb * 2 + half];
                #pragma unroll
                for (int nb = 0; nb < 8; nb++) {
                    int col0 = warp_ns + nb * 8 + 2 * qd;
                    int cbuf = col0 >> 5, c5 = col0 & 31;
                    uint32_t addr = APS + cbuf * 16384 +
                        (uint32_t)(row * 128 + (((c5 >> 2) ^ (row & 7)) * 16) + (c5 & 3) * 4);
                    uint2 u = make_uint2(f2tf(sacc[mb][nb][half * 2 + 0]),
                                         f2tf(sacc[mb][nb][half * 2 + 1]));
                    *(uint2*)(smem + addr) = u;
                }
            }
        __syncthreads();

        #pragma unroll
        for (int ksx = 0; ksx < 16; ksx++) {
            const uint32_t Pb = sb + APS + (ksx >> 2) * 16384;
            const uint32_t Vb = sb + AVT + (ksx >> 2) * 8192;
            const int kk = ksx & 3;
            uint32_t afr[2][4], bfr[4][2];
            #pragma unroll
            for (int mb = 0; mb < 2; mb++) {
                int row = warp_m + mb * 16 + rowA;
                int quad = (2 * kk + qselA) ^ (rowA & 7);
                ldsm4(afr[mb][0], afr[mb][1], afr[mb][2], afr[mb][3],
                      Pb + (uint32_t)(row * 128 + quad * 16));
            }
            #pragma unroll
            for (int s = 0; s < 2; s++) {
                int nb = 2 * s + (matB >> 1);
                int n = warp_np + nb * 8 + lane7;
                int quad = (2 * kk + (matB & 1)) ^ lane7;
                ldsm4(bfr[2*s][0], bfr[2*s][1], bfr[2*s+1][0], bfr[2*s+1][1],
                      Vb + (uint32_t)(n * 128 + quad * 16));
            }
            #pragma unroll
            for (int mb = 0; mb < 2; mb++)
                #pragma unroll
                for (int nb = 0; nb < 4; nb++)
                    mma8(o[mb][nb], afr[mb], bfr[nb]);
        }
    }

    float inv[4];
    #pragma unroll
    for (int i = 0; i < 4; i++) inv[i] = 1.0f / lsum[i];
    #pragma unroll
    for (int mb = 0; mb < 2; mb++)
        #pragma unroll
        for (int half = 0; half < 2; half++) {
            int i = mb * 2 + half;
            int row = q0 + rloc[i];
            #pragma unroll
            for (int nb = 0; nb < 4; nb++) {
                int col = warp_np + nb * 8 + 2 * qd;
                *(__half2*)&g_atth[((size_t)b * TT + row) * DD + h * HD + col] =
                    __floats2half2_rn(o[mb][nb][half * 2 + 0] * inv[i],
                                      o[mb][nb][half * 2 + 1] * inv[i]);
            }
        }
}

// ---------------- launch -------------------------------------------------
extern "C" void kernel_launch(void* const* d_in, const int* in_sizes, int n_in,
                              void* d_out, int out_size) {
    const float* x     = (const float*)d_in[0];
    const float* w_qkv = (const float*)d_in[1];
    const float* b_qkv = (const float*)d_in[2];
    const float* w_fc  = (const float*)d_in[3];
    const float* b_fc  = (const float*)d_in[4];
    const float* ln1_g = (const float*)d_in[5];
    const float* ln1_b = (const float*)d_in[6];
    const float* ln2_g = (const float*)d_in[7];
    const float* ln2_b = (const float*)d_in[8];
    const float* w1    = (const float*)d_in[9];
    const float* b1    = (const float*)d_in[10];
    const float* w2    = (const float*)d_in[11];
    const float* b2    = (const float*)d_in[12];
    float* out = (float*)d_out;

    __half *p_hh, *p_atth, *p_midh, *p_wqkvT, *p_wfcT, *p_w1T, *p_w2T;
    float *p_qkv, *p_x1;
    cudaGetSymbolAddress((void**)&p_hh,   g_hh);
    cudaGetSymbolAddress((void**)&p_qkv,  g_qkv);
    cudaGetSymbolAddress((void**)&p_atth, g_atth);
    cudaGetSymbolAddress((void**)&p_x1,   g_x1);
    cudaGetSymbolAddress((void**)&p_midh, g_midh);
    cudaGetSymbolAddress((void**)&p_wqkvT, g_wqkvT);
    cudaGetSymbolAddress((void**)&p_wfcT,  g_wfcT);
    cudaGetSymbolAddress((void**)&p_w1T,   g_w1T);
    cudaGetSymbolAddress((void**)&p_w2T,   g_w2T);

    cudaFuncSetAttribute(gemm_h<0>, cudaFuncAttributeMaxDynamicSharedMemorySize, GSMEM);
    cudaFuncSetAttribute(gemm_h<1>, cudaFuncAttributeMaxDynamicSharedMemorySize, GSMEM);
    cudaFuncSetAttribute(gemm_h<2>, cudaFuncAttributeMaxDynamicSharedMemorySize, GSMEM);
    cudaFuncSetAttribute(attn_mma,  cudaFuncAttributeMaxDynamicSharedMemorySize, ATT_SMEM);

    dim3 tb(32, 8);
    // 0) transpose weights (fp32 -> half, [N,K])
    transpose_kernel<<<dim3(DD/32, 3*DD/32), tb>>>(w_qkv, p_wqkvT, DD, 3*DD);
    transpose_kernel<<<dim3(DD/32, DD/32),   tb>>>(w_fc,  p_wfcT,  DD, DD);
    transpose_kernel<<<dim3(DD/32, 4*DD/32), tb>>>(w1,    p_w1T,   DD, 4*DD);
    transpose_kernel<<<dim3(4*DD/32, DD/32), tb>>>(w2,    p_w2T,   4*DD, DD);

    // 1) h = LN1(x)  (half)
    ln_kernel<<<ROWS, 256>>>(x, ln1_g, ln1_b, p_hh);

    // 2) qkv = h @ w_qkv + b_qkv   [4096 x 3072] fp32 out
    //    (res unused under EPI0 -> pass x; Ch unused -> pass p_midh)
    gemm_h<0><<<dim3(3*DD/128, ROWS/128), 256, GSMEM>>>(
        p_hh, p_wqkvT, b_qkv, x, p_qkv, p_midh, ROWS, 3*DD, DD);

    // 3) causal attention -> g_atth (half)
    attn_mma<<<dim3(TT/128, BB*HH), 256, ATT_SMEM>>>();

    // 4) x1 = x + att @ w_fc + b_fc  [4096 x 1024] fp32 out (Ch unused)
    gemm_h<1><<<dim3(DD/128, ROWS/128), 256, GSMEM>>>(
        p_atth, p_wfcT, b_fc, x, p_x1, p_midh, ROWS, DD, DD);

    // 5) h = LN2(x1)  (half)
    ln_kernel<<<ROWS, 256>>>(p_x1, ln2_g, ln2_b, p_hh);

    // 6) mid = gelu(h @ w1 + b1)   [4096 x 4096] half out
    //    (res unused -> pass x; C unused -> pass p_qkv scratch)
    gemm_h<2><<<dim3(4*DD/128, ROWS/128), 256, GSMEM>>>(
        p_hh, p_w1T, b1, x, p_qkv, p_midh, ROWS, 4*DD, DD);

    // 7) out = x1 + mid @ w2 + b2  [4096 x 1024] fp32 out (Ch unused)
    gemm_h<1><<<dim3(DD/128, ROWS/128), 256, GSMEM>>>(
        p_midh, p_w2T, b2, p_x1, out, p_wqkvT, ROWS, DD, 4*DD);
}